// round 3
// baseline (speedup 1.0000x reference)
#include <cuda_runtime.h>
#include <math.h>

// ---------------------------------------------------------------------------
// StackedLSTM: B=2, T=4096, D1=40, H=64, G=4H=256
//   stack1: 3-layer LSTM -> attention stats (max/mean/std over H) ->
//   conv(3->3)->BN->relu -> conv(3->5)->BN->relu -> conv(5->5)->BN->relu ->
//   conv(5->1)->BN -> sigmoid gate added to H -> stack2: 3-layer LSTM ->
//   fc(64->64) -> fc(64->1) -> sigmoid  => out [B,T]
//
// Structure: per layer, a parallel GEMM hoists xg = X@Wih^T + b (as in the
// reference), then a persistent per-batch scan block runs the recurrence with
// packed f32x2 FMAs and the Whh row held in registers.
// ---------------------------------------------------------------------------

#define BB 2
#define TT 4096
#define DD1 40
#define HH 64
#define GG 256
#define KC 11

// ---- device scratch (no allocations allowed) ----
__device__ float g_xg[BB * TT * GG];        // 8 MB input-projection buffer
__device__ float g_bufA[BB * TT * HH];      // 2 MB ping
__device__ float g_bufB[BB * TT * HH];      // 2 MB pong
__device__ float g_att[BB * 3 * TT];        // attention stats [B,3,T]
__device__ float g_cva[BB * 5 * TT];        // conv ping
__device__ float g_cvb[BB * 5 * TT];        // conv pong
__device__ float g_stats[16];               // per-channel (mean, rstd)

__device__ __forceinline__ float fsig(float x) {
    return 1.0f / (1.0f + __expf(-x));
}
__device__ __forceinline__ float ftanh(float x) {
    // tanh(x) = sign(x) * (1 - 2/(e^{2|x|}+1)); saturates cleanly (no NaN)
    float e = __expf(2.0f * fabsf(x));
    float r = 1.0f - 2.0f / (e + 1.0f);
    return copysignf(r, x);
}

// ---------------------------------------------------------------------------
// xg = X @ Wih^T + b   — X: [B,T,IN], Wih: [G,IN], b: [G] -> g_xg [B,T,G]
// grid = B*T/TS, block = 256 (one gate row per thread)
// ---------------------------------------------------------------------------
template <int IN, int TS>
__global__ void __launch_bounds__(256) xg_gemm(
    const float* __restrict__ X, const float* __restrict__ Wih,
    const float* __restrict__ bias)
{
    __shared__ float xs[TS * IN];
    const int tid = threadIdx.x;  // gate row 0..255
    const int blocksPerB = TT / TS;
    const int b  = blockIdx.x / blocksPerB;
    const int t0 = (blockIdx.x % blocksPerB) * TS;

    const float* xrow = X + ((size_t)b * TT + t0) * IN;
    for (int i = tid; i < TS * IN; i += 256) xs[i] = xrow[i];

    float w[IN];
#pragma unroll
    for (int i = 0; i < IN; i++) w[i] = Wih[tid * IN + i];
    const float bv = bias[tid];
    __syncthreads();

#pragma unroll 1
    for (int ts = 0; ts < TS; ts++) {
        float acc = bv;
#pragma unroll
        for (int i = 0; i < IN; i++) acc = fmaf(xs[ts * IN + i], w[i], acc);
        g_xg[((size_t)b * TT + t0 + ts) * GG + tid] = acc;
    }
}

// ---------------------------------------------------------------------------
// LSTM recurrence scan. grid = B (one CTA per batch), block = 256 (one gate
// row per thread). g accumulated with packed fma.rn.f32x2 (FFMA2).
// Reads xg from g_xg (prefetched 2 steps ahead), writes h sequence to Hout.
// ---------------------------------------------------------------------------
__global__ void __launch_bounds__(256, 1) lstm_scan(
    const float* __restrict__ Whh,   // [G,H] layer slice
    const float* __restrict__ h0,    // [B,H] layer slice
    const float* __restrict__ c0,    // [B,H] layer slice
    float* __restrict__ Hout)        // [B,T,H]
{
    __shared__ __align__(16) float h_sm[HH];
    __shared__ float act_s[GG];

    const int tid = threadIdx.x;
    const int b   = blockIdx.x;
    const int gt  = tid >> 6;  // 0=i 1=f 2=g 3=o

    // Whh row for this gate element, packed as 32 x f32x2
    unsigned long long wq[32];
    const unsigned long long* wp =
        (const unsigned long long*)(Whh + tid * HH);
#pragma unroll
    for (int k = 0; k < 32; k++) wq[k] = wp[k];

    float c = 0.0f;
    if (tid < HH) {
        h_sm[tid] = h0[b * HH + tid];
        c         = c0[b * HH + tid];
    }
    __syncthreads();

    const float* xcol = g_xg + (size_t)b * TT * GG + tid;
    float xv0 = xcol[0];
    float xv1 = xcol[GG];
    const unsigned long long* h8 = (const unsigned long long*)h_sm;

#pragma unroll 1
    for (int t = 0; t < TT; t++) {
        const float xv = xv0;
        xv0 = xv1;
        xv1 = (t + 2 < TT) ? xcol[(size_t)(t + 2) * GG] : 0.0f;

        unsigned long long a0 = 0ull, a1 = 0ull, a2 = 0ull, a3 = 0ull;
#pragma unroll
        for (int k = 0; k < 32; k += 4) {
            unsigned long long hq0 = h8[k],     hq1 = h8[k + 1];
            unsigned long long hq2 = h8[k + 2], hq3 = h8[k + 3];
            asm("fma.rn.f32x2 %0, %1, %2, %0;" : "+l"(a0) : "l"(wq[k])     , "l"(hq0));
            asm("fma.rn.f32x2 %0, %1, %2, %0;" : "+l"(a1) : "l"(wq[k + 1]) , "l"(hq1));
            asm("fma.rn.f32x2 %0, %1, %2, %0;" : "+l"(a2) : "l"(wq[k + 2]) , "l"(hq2));
            asm("fma.rn.f32x2 %0, %1, %2, %0;" : "+l"(a3) : "l"(wq[k + 3]) , "l"(hq3));
        }
        float2 f0, f1, f2, f3;
        asm("mov.b64 {%0,%1}, %2;" : "=f"(f0.x), "=f"(f0.y) : "l"(a0));
        asm("mov.b64 {%0,%1}, %2;" : "=f"(f1.x), "=f"(f1.y) : "l"(a1));
        asm("mov.b64 {%0,%1}, %2;" : "=f"(f2.x), "=f"(f2.y) : "l"(a2));
        asm("mov.b64 {%0,%1}, %2;" : "=f"(f3.x), "=f"(f3.y) : "l"(a3));
        float s = (((f0.x + f0.y) + (f1.x + f1.y)) +
                   ((f2.x + f2.y) + (f3.x + f3.y))) + xv;

        // activation applied by the thread that computed the row
        float a = (gt == 2) ? ftanh(s) : fsig(s);
        act_s[tid] = a;
        __syncthreads();

        if (tid < HH) {
            const float ai = act_s[tid];
            const float af = act_s[HH + tid];
            const float ag = act_s[2 * HH + tid];
            const float ao = act_s[3 * HH + tid];
            c = fmaf(af, c, ai * ag);
            const float hv = ao * ftanh(c);
            h_sm[tid] = hv;
            Hout[((size_t)b * TT + t) * HH + tid] = hv;
        }
        __syncthreads();
    }
}

// ---------------------------------------------------------------------------
// attention stats: per (b,t): max / mean / unbiased-std over H -> [B,3,T]
// one warp per row. grid = B*T/8, block 256.
// ---------------------------------------------------------------------------
__global__ void att_stats(const float* __restrict__ Hin, float* __restrict__ hc)
{
    const int warp = threadIdx.x >> 5, lane = threadIdx.x & 31;
    const int row  = blockIdx.x * 8 + warp;  // 0..B*T-1
    const float* hr = Hin + (size_t)row * HH;
    float v0 = hr[lane], v1 = hr[lane + 32];
    float mx = fmaxf(v0, v1);
    float s  = v0 + v1;
    float sq = v0 * v0 + v1 * v1;
#pragma unroll
    for (int o = 16; o > 0; o >>= 1) {
        mx = fmaxf(mx, __shfl_xor_sync(0xffffffffu, mx, o));
        s  += __shfl_xor_sync(0xffffffffu, s, o);
        sq += __shfl_xor_sync(0xffffffffu, sq, o);
    }
    if (lane == 0) {
        const int b = row / TT, t = row % TT;
        const float mean = s * (1.0f / 64.0f);
        float var = (sq - 64.0f * mean * mean) * (1.0f / 63.0f);
        var = fmaxf(var, 0.0f);
        hc[(b * 3 + 0) * TT + t] = mx;
        hc[(b * 3 + 1) * TT + t] = mean;
        hc[(b * 3 + 2) * TT + t] = sqrtf(var);
    }
}

// ---------------------------------------------------------------------------
// conv1d 'same' (K=11, pad 5) with optional fused BN(+relu) on the INPUT.
// Zero padding applies in the post-BN/relu domain (matches reference order).
// ---------------------------------------------------------------------------
__global__ void conv1d_k(const float* __restrict__ in, int Cin,
                         const float* __restrict__ w, const float* __restrict__ bias,
                         int Cout, const float* __restrict__ stats, int relu,
                         float* __restrict__ out)
{
    const int idx = blockIdx.x * blockDim.x + threadIdx.x;
    if (idx >= BB * Cout * TT) return;
    const int t = idx % TT;
    const int o = (idx / TT) % Cout;
    const int b = idx / (TT * Cout);
    float acc = bias[o];
    for (int ci = 0; ci < Cin; ci++) {
        float m = 0.0f, r = 1.0f;
        if (stats) { m = stats[ci * 2]; r = stats[ci * 2 + 1]; }
        const float* xr = in + ((size_t)b * Cin + ci) * TT;
        const float* wr = w + (o * Cin + ci) * KC;
#pragma unroll
        for (int k = 0; k < KC; k++) {
            const int tt = t + k - 5;
            float xv = 0.0f;
            if (tt >= 0 && tt < TT) {
                xv = xr[tt];
                if (stats) xv = (xv - m) * r;
                if (relu) xv = fmaxf(xv, 0.0f);
            }
            acc = fmaf(xv, wr[k], acc);
        }
    }
    out[idx] = acc;
}

// per-channel batch stats over (B,T): mean & rsqrt(var_biased + 1e-5)
__global__ void bn_stats(const float* __restrict__ x, int C)
{
    __shared__ float ss[256], sqs[256];
    const int ch = blockIdx.x, tid = threadIdx.x;
    float s = 0.0f, q = 0.0f;
    for (int b = 0; b < BB; b++) {
        const float* xr = x + ((size_t)b * C + ch) * TT;
        for (int t = tid; t < TT; t += 256) {
            const float v = xr[t];
            s += v;
            q = fmaf(v, v, q);
        }
    }
    ss[tid] = s; sqs[tid] = q;
    __syncthreads();
    for (int o = 128; o > 0; o >>= 1) {
        if (tid < o) { ss[tid] += ss[tid + o]; sqs[tid] += sqs[tid + o]; }
        __syncthreads();
    }
    if (tid == 0) {
        const float n = (float)(BB * TT);
        const float mean = ss[0] / n;
        const float var = sqs[0] / n - mean * mean;
        g_stats[ch * 2]     = mean;
        g_stats[ch * 2 + 1] = rsqrtf(fmaxf(var, 0.0f) + 1e-5f);
    }
}

// Hp = H1 + sigmoid(BN(conv4 output)) broadcast over hidden dim
__global__ void gate_add(const float* __restrict__ H1,
                         const float* __restrict__ x4,  // [B,1,T]
                         float* __restrict__ Hp)
{
    const int idx = blockIdx.x * 256 + threadIdx.x;
    if (idx >= BB * TT * HH) return;
    const int row = idx / HH;  // b*T + t
    const int b = row / TT, t = row % TT;
    const float xv = (x4[(size_t)b * TT + t] - g_stats[0]) * g_stats[1];
    Hp[idx] = H1[idx] + fsig(xv);
}

// fused fc1->fc2->sigmoid: collapse into out2 @ w_eff + b_eff (no nonlinearity
// between the fc layers). One warp per row. grid = B*T/128, block 256.
__global__ void final_fc(const float* __restrict__ out2,
                         const float* __restrict__ fc1w, const float* __restrict__ fc1b,
                         const float* __restrict__ fc2w, const float* __restrict__ fc2b,
                         float* __restrict__ dout)
{
    __shared__ float we[HH];
    __shared__ float beff;
    const int tid = threadIdx.x;
    if (tid < HH) {
        float s = 0.0f;
        for (int k = 0; k < HH; k++) s = fmaf(fc2w[k], fc1w[k * HH + tid], s);
        we[tid] = s;
    }
    if (tid == 64) {
        float s = fc2b[0];
        for (int k = 0; k < HH; k++) s = fmaf(fc1b[k], fc2w[k], s);
        beff = s;
    }
    __syncthreads();
    const int warp = tid >> 5, lane = tid & 31;
    const int base = blockIdx.x * 128 + warp * 16;
#pragma unroll 1
    for (int r = 0; r < 16; r++) {
        const int row = base + r;
        const float* xr = out2 + (size_t)row * HH;
        float v = xr[lane] * we[lane] + xr[lane + 32] * we[lane + 32];
#pragma unroll
        for (int o = 16; o > 0; o >>= 1) v += __shfl_xor_sync(0xffffffffu, v, o);
        if (lane == 0) dout[row] = fsig(v + beff);
    }
}

// ---------------------------------------------------------------------------
extern "C" void kernel_launch(void* const* d_in, const int* in_sizes, int n_in,
                              void* d_out, int out_size)
{
    const float* data  = (const float*)d_in[0];
    const float* h01   = (const float*)d_in[1];
    const float* c01   = (const float*)d_in[2];
    const float* h02   = (const float*)d_in[3];
    const float* c02   = (const float*)d_in[4];
    const float* Wih0  = (const float*)d_in[5];   // [256,40]
    const float* Wih12 = (const float*)d_in[6];   // [2,256,64]
    const float* l1Whh = (const float*)d_in[7];   // [3,256,64]
    const float* l1b   = (const float*)d_in[8];   // [3,256]
    const float* l2Wih = (const float*)d_in[9];   // [3,256,64]
    const float* l2Whh = (const float*)d_in[10];  // [3,256,64]
    const float* l2b   = (const float*)d_in[11];  // [3,256]
    const float* cw1 = (const float*)d_in[12];
    const float* cb1 = (const float*)d_in[13];
    const float* cw2 = (const float*)d_in[14];
    const float* cb2 = (const float*)d_in[15];
    const float* cw3 = (const float*)d_in[16];
    const float* cb3 = (const float*)d_in[17];
    const float* cw4 = (const float*)d_in[18];
    const float* cb4 = (const float*)d_in[19];
    const float* fc1w = (const float*)d_in[20];
    const float* fc1b = (const float*)d_in[21];
    const float* fc2w = (const float*)d_in[22];
    const float* fc2b = (const float*)d_in[23];
    float* out = (float*)d_out;

    float *bufA, *bufB, *att, *cva, *cvb, *stats;
    cudaGetSymbolAddress((void**)&bufA, g_bufA);
    cudaGetSymbolAddress((void**)&bufB, g_bufB);
    cudaGetSymbolAddress((void**)&att,  g_att);
    cudaGetSymbolAddress((void**)&cva,  g_cva);
    cudaGetSymbolAddress((void**)&cvb,  g_cvb);
    cudaGetSymbolAddress((void**)&stats, g_stats);

    const int GEMM_GRID = BB * TT / 16;

    // ----- stack 1 -----
    xg_gemm<DD1, 16><<<GEMM_GRID, 256>>>(data, Wih0, l1b);
    lstm_scan<<<BB, 256>>>(l1Whh, h01, c01, bufA);
    xg_gemm<HH, 16><<<GEMM_GRID, 256>>>(bufA, Wih12, l1b + GG);
    lstm_scan<<<BB, 256>>>(l1Whh + GG * HH, h01 + BB * HH, c01 + BB * HH, bufB);
    xg_gemm<HH, 16><<<GEMM_GRID, 256>>>(bufB, Wih12 + GG * HH, l1b + 2 * GG);
    lstm_scan<<<BB, 256>>>(l1Whh + 2 * GG * HH, h01 + 2 * BB * HH, c01 + 2 * BB * HH, bufA);

    // ----- attention conv gate -----
    att_stats<<<BB * TT / 8, 256>>>(bufA, att);
    conv1d_k<<<(BB * 3 * TT + 255) / 256, 256>>>(att, 3, cw1, cb1, 3, nullptr, 0, cva);
    bn_stats<<<3, 256>>>(cva, 3);
    conv1d_k<<<(BB * 5 * TT + 255) / 256, 256>>>(cva, 3, cw2, cb2, 5, stats, 1, cvb);
    bn_stats<<<5, 256>>>(cvb, 5);
    conv1d_k<<<(BB * 5 * TT + 255) / 256, 256>>>(cvb, 5, cw3, cb3, 5, stats, 1, cva);
    bn_stats<<<5, 256>>>(cva, 5);
    conv1d_k<<<(BB * 1 * TT + 255) / 256, 256>>>(cva, 5, cw4, cb4, 1, stats, 1, cvb);
    bn_stats<<<1, 256>>>(cvb, 1);
    gate_add<<<BB * TT * HH / 256, 256>>>(bufA, cvb, bufB);

    // ----- stack 2 -----
    xg_gemm<HH, 16><<<GEMM_GRID, 256>>>(bufB, l2Wih, l2b);
    lstm_scan<<<BB, 256>>>(l2Whh, h02, c02, bufA);
    xg_gemm<HH, 16><<<GEMM_GRID, 256>>>(bufA, l2Wih + GG * HH, l2b + GG);
    lstm_scan<<<BB, 256>>>(l2Whh + GG * HH, h02 + BB * HH, c02 + BB * HH, bufB);
    xg_gemm<HH, 16><<<GEMM_GRID, 256>>>(bufB, l2Wih + 2 * GG * HH, l2b + 2 * GG);
    lstm_scan<<<BB, 256>>>(l2Whh + 2 * GG * HH, h02 + 2 * BB * HH, c02 + 2 * BB * HH, bufA);

    // ----- head -----
    final_fc<<<BB * TT / 128, 256>>>(bufA, fc1w, fc1b, fc2w, fc2b, out);
}

// round 16
// speedup vs baseline: 1.9931x; 1.9931x over previous
#include <cuda_runtime.h>
#include <math.h>

// ---------------------------------------------------------------------------
// StackedLSTM: B=2, T=4096, D1=40, H=64, G=4H=256
// Round 15: phase-launched wavefront. The 3-layer LSTM stack is pipelined
// across layers in chunks of CH=128 timesteps; each pipeline phase is a
// SEPARATE kernel launch (6 CTAs: layer x batch), so every inter-layer and
// inter-phase dependency is ordered by the kernel boundary (full fence, L1D
// flushed per launch on sm_103a). No polling, no device-side grid barrier.
// Step core = R3-proven (tid = gate row, act_s exchange, 2 barriers) with
// fused Wih.h_prev for layers 1,2, LDS.128 operand loads, and fast-division
// activations.
// ---------------------------------------------------------------------------

#define BB 2
#define TT 4096
#define DD1 40
#define HH 64
#define GG 256
#define KC 11
#define CH 128
#define NCH (TT / CH)     // 32 chunks
#define NPH (NCH + 2)     // 34 phases (3-deep pipeline)

// ---- device scratch (no allocations allowed) ----
__device__ float g_xg[BB * TT * GG];        // 8 MB input-projection (layer 0)
__device__ float g_hA[BB * TT * HH];        // layer0 -> layer1 h stream
__device__ float g_hB[BB * TT * HH];        // layer1 -> layer2 h stream
__device__ float g_bufA[BB * TT * HH];      // stack outputs
__device__ float g_bufB[BB * TT * HH];      // gated input to stack2
__device__ float g_att[BB * 3 * TT];        // attention stats [B,3,T]
__device__ float g_cva[BB * 5 * TT];        // conv ping
__device__ float g_cvb[BB * 5 * TT];        // conv pong
__device__ float g_stats[16];               // per-channel (mean, rstd)
__device__ float g_state_h[3 * BB * HH];    // per-(layer,b) carried h
__device__ float g_state_c[3 * BB * HH];    // per-(layer,b) carried c

__device__ __forceinline__ float fsig(float x) {
    return __fdividef(1.0f, 1.0f + __expf(-x));
}
__device__ __forceinline__ float ftanh(float x) {
    float e = __expf(2.0f * fabsf(x));
    float r = 1.0f - __fdividef(2.0f, e + 1.0f);
    return copysignf(r, x);
}

// copy the stack's initial h/c into the carried-state arrays
__global__ void init_state(const float* __restrict__ h0,
                           const float* __restrict__ c0)
{
    const int i = threadIdx.x;  // 0..383
    if (i < 3 * BB * HH) {
        g_state_h[i] = h0[i];
        g_state_c[i] = c0[i];
    }
}

// ---------------------------------------------------------------------------
// xg = X @ Wih^T + b for layer 0 of a stack (input known up front)
// ---------------------------------------------------------------------------
template <int IN, int TS>
__global__ void __launch_bounds__(256) xg_gemm(
    const float* __restrict__ X, const float* __restrict__ Wih,
    const float* __restrict__ bias)
{
    __shared__ float xs[TS * IN];
    const int tid = threadIdx.x;
    const int blocksPerB = TT / TS;
    const int b  = blockIdx.x / blocksPerB;
    const int t0 = (blockIdx.x % blocksPerB) * TS;

    const float* xrow = X + ((size_t)b * TT + t0) * IN;
    for (int i = tid; i < TS * IN; i += 256) xs[i] = xrow[i];

    float w[IN];
#pragma unroll
    for (int i = 0; i < IN; i++) w[i] = Wih[tid * IN + i];
    const float bv = bias[tid];
    __syncthreads();

#pragma unroll 1
    for (int ts = 0; ts < TS; ts++) {
        float acc = bv;
#pragma unroll
        for (int i = 0; i < IN; i++) acc = fmaf(xs[ts * IN + i], w[i], acc);
        g_xg[((size_t)b * TT + t0 + ts) * GG + tid] = acc;
    }
}

// ---------------------------------------------------------------------------
// One pipeline phase: CTA (layer,b) processes chunk ci = ph - layer (if
// valid). All data this phase consumes was produced in PREVIOUS LAUNCHES.
// ---------------------------------------------------------------------------
#define FMA2(acc, w, h) asm("fma.rn.f32x2 %0, %1, %2, %0;" : "+l"(acc) : "l"(w), "l"(h))
#define UNPK(a, x, y)   asm("mov.b64 {%0,%1}, %2;" : "=f"(x), "=f"(y) : "l"(a))

__global__ void __launch_bounds__(256, 1) stack_phase(
    int ph,
    const float* __restrict__ Whh_all,  // [3,G,H]
    const float* __restrict__ Wih12,    // [2,G,H] (layers 1,2)
    const float* __restrict__ b12,      // [2,G]
    float* __restrict__ Hfin)           // [B,T,H] final layer output
{
    const int layer = blockIdx.x >> 1;
    const int b     = blockIdx.x & 1;
    const int ci    = ph - layer;
    if (ci < 0 || ci >= NCH) return;

    __shared__ __align__(16) float h_sm[HH];
    __shared__ float act_s[GG];
    __shared__ __align__(16) float chunk_sm[CH * HH];   // 32 KB staged h_prev

    const int tid = threadIdx.x;       // gate row 0..255
    const int gt  = tid >> 6;          // 0=i 1=f 2=g 3=o
    const bool fused = (layer > 0);
    const int tbase  = ci * CH;
    const int sidx   = (layer * BB + b) * HH;

    const float* prev = ((layer == 1) ? g_hA : g_hB) + (size_t)b * TT * HH;
    float* outp = ((layer == 0) ? g_hA : (layer == 1) ? g_hB : Hfin)
                  + (size_t)b * TT * HH;

    // weights in registers, packed as ulonglong2 (16B loads)
    ulonglong2 wq[16], wp[16];
    {
        const ulonglong2* whp =
            (const ulonglong2*)(Whh_all + ((size_t)layer * GG + tid) * HH);
#pragma unroll
        for (int k = 0; k < 16; k++) wq[k] = whp[k];
        if (fused) {
            const ulonglong2* wip =
                (const ulonglong2*)(Wih12 + ((size_t)(layer - 1) * GG + tid) * HH);
#pragma unroll
            for (int k = 0; k < 16; k++) wp[k] = wip[k];
        }
    }
    const float xbias = fused ? b12[(layer - 1) * GG + tid] : 0.0f;

    // stage h_prev chunk (written by producer layer in a previous launch)
    if (fused) {
        const float4* src = (const float4*)(prev + (size_t)tbase * HH);
        float4* dst = (float4*)chunk_sm;
#pragma unroll
        for (int i = 0; i < (CH * HH / 4) / 256; i++)
            dst[tid + i * 256] = src[tid + i * 256];
    }

    // carried state
    float c = 0.0f;
    if (tid < HH) {
        h_sm[tid] = g_state_h[sidx + tid];
        c         = g_state_c[sidx + tid];
    }

    // layer 0: xg stream prefetch (distance 2)
    const float* xcol = g_xg + (size_t)b * TT * GG + tid;
    float xv0 = 0.0f, xv1 = 0.0f;
    if (!fused) {
        xv0 = xcol[(size_t)tbase * GG];
        xv1 = xcol[(size_t)(tbase + 1) * GG];
    }
    __syncthreads();

#pragma unroll 1
    for (int s_ = 0; s_ < CH; s_++) {
        const int t = tbase + s_;

        float xv;
        if (!fused) {
            xv  = xv0;
            xv0 = xv1;
            xv1 = ((t + 2) < TT) ? xcol[(size_t)(t + 2) * GG] : 0.0f;
        } else {
            xv = xbias;
        }

        const ulonglong2* h16 = (const ulonglong2*)h_sm;
        unsigned long long a0 = 0ull, a1 = 0ull, a2 = 0ull, a3 = 0ull;
        unsigned long long a4 = 0ull, a5 = 0ull, a6 = 0ull, a7 = 0ull;
#pragma unroll
        for (int k = 0; k < 16; k += 4) {
            ulonglong2 p0 = h16[k],     p1 = h16[k + 1];
            ulonglong2 p2 = h16[k + 2], p3 = h16[k + 3];
            FMA2(a0, wq[k + 0].x, p0.x); FMA2(a1, wq[k + 0].y, p0.y);
            FMA2(a2, wq[k + 1].x, p1.x); FMA2(a3, wq[k + 1].y, p1.y);
            FMA2(a4, wq[k + 2].x, p2.x); FMA2(a5, wq[k + 2].y, p2.y);
            FMA2(a6, wq[k + 3].x, p3.x); FMA2(a7, wq[k + 3].y, p3.y);
        }
        if (fused) {
            const ulonglong2* q16 = (const ulonglong2*)(chunk_sm + s_ * HH);
#pragma unroll
            for (int k = 0; k < 16; k += 4) {
                ulonglong2 p0 = q16[k],     p1 = q16[k + 1];
                ulonglong2 p2 = q16[k + 2], p3 = q16[k + 3];
                FMA2(a0, wp[k + 0].x, p0.x); FMA2(a1, wp[k + 0].y, p0.y);
                FMA2(a2, wp[k + 1].x, p1.x); FMA2(a3, wp[k + 1].y, p1.y);
                FMA2(a4, wp[k + 2].x, p2.x); FMA2(a5, wp[k + 2].y, p2.y);
                FMA2(a6, wp[k + 3].x, p3.x); FMA2(a7, wp[k + 3].y, p3.y);
            }
        }
        float u0, u1, u2, u3, u4, u5, u6, u7;
        float v0, v1, v2, v3, v4, v5, v6, v7;
        UNPK(a0, u0, v0); UNPK(a1, u1, v1); UNPK(a2, u2, v2); UNPK(a3, u3, v3);
        UNPK(a4, u4, v4); UNPK(a5, u5, v5); UNPK(a6, u6, v6); UNPK(a7, u7, v7);
        const float s =
            ((((u0 + v0) + (u1 + v1)) + ((u2 + v2) + (u3 + v3))) +
             (((u4 + v4) + (u5 + v5)) + ((u6 + v6) + (u7 + v7)))) + xv;

        act_s[tid] = (gt == 2) ? ftanh(s) : fsig(s);
        __syncthreads();

        if (tid < HH) {
            const float ai = act_s[tid];
            const float af = act_s[HH + tid];
            const float ag = act_s[2 * HH + tid];
            const float ao = act_s[3 * HH + tid];
            c = fmaf(af, c, ai * ag);
            const float hv = ao * ftanh(c);
            h_sm[tid] = hv;
            outp[(size_t)t * HH + tid] = hv;
        }
        __syncthreads();
    }

    // save carried state for the next phase of this (layer,b)
    if (tid < HH) {
        g_state_h[sidx + tid] = h_sm[tid];
        g_state_c[sidx + tid] = c;
    }
}

// ---------------------------------------------------------------------------
// attention stats: per (b,t): max / mean / unbiased-std over H -> [B,3,T]
// ---------------------------------------------------------------------------
__global__ void att_stats(const float* __restrict__ Hin, float* __restrict__ hc)
{
    const int warp = threadIdx.x >> 5, lane = threadIdx.x & 31;
    const int row  = blockIdx.x * 8 + warp;
    const float* hr = Hin + (size_t)row * HH;
    float v0 = hr[lane], v1 = hr[lane + 32];
    float mx = fmaxf(v0, v1);
    float s  = v0 + v1;
    float sq = v0 * v0 + v1 * v1;
#pragma unroll
    for (int o = 16; o > 0; o >>= 1) {
        mx = fmaxf(mx, __shfl_xor_sync(0xffffffffu, mx, o));
        s  += __shfl_xor_sync(0xffffffffu, s, o);
        sq += __shfl_xor_sync(0xffffffffu, sq, o);
    }
    if (lane == 0) {
        const int b = row / TT, t = row % TT;
        const float mean = s * (1.0f / 64.0f);
        float var = (sq - 64.0f * mean * mean) * (1.0f / 63.0f);
        var = fmaxf(var, 0.0f);
        hc[(b * 3 + 0) * TT + t] = mx;
        hc[(b * 3 + 1) * TT + t] = mean;
        hc[(b * 3 + 2) * TT + t] = sqrtf(var);
    }
}

// conv1d 'same' (K=11) with optional fused BN(+relu) on the INPUT.
__global__ void conv1d_k(const float* __restrict__ in, int Cin,
                         const float* __restrict__ w, const float* __restrict__ bias,
                         int Cout, const float* __restrict__ stats, int relu,
                         float* __restrict__ out)
{
    const int idx = blockIdx.x * blockDim.x + threadIdx.x;
    if (idx >= BB * Cout * TT) return;
    const int t = idx % TT;
    const int o = (idx / TT) % Cout;
    const int b = idx / (TT * Cout);
    float acc = bias[o];
    for (int ci = 0; ci < Cin; ci++) {
        float m = 0.0f, r = 1.0f;
        if (stats) { m = stats[ci * 2]; r = stats[ci * 2 + 1]; }
        const float* xr = in + ((size_t)b * Cin + ci) * TT;
        const float* wr = w + (o * Cin + ci) * KC;
#pragma unroll
        for (int k = 0; k < KC; k++) {
            const int tt = t + k - 5;
            float xv = 0.0f;
            if (tt >= 0 && tt < TT) {
                xv = xr[tt];
                if (stats) xv = (xv - m) * r;
                if (relu) xv = fmaxf(xv, 0.0f);
            }
            acc = fmaf(xv, wr[k], acc);
        }
    }
    out[idx] = acc;
}

__global__ void bn_stats(const float* __restrict__ x, int C)
{
    __shared__ float ss[256], sqs[256];
    const int ch = blockIdx.x, tid = threadIdx.x;
    float s = 0.0f, q = 0.0f;
    for (int b = 0; b < BB; b++) {
        const float* xr = x + ((size_t)b * C + ch) * TT;
        for (int t = tid; t < TT; t += 256) {
            const float v = xr[t];
            s += v;
            q = fmaf(v, v, q);
        }
    }
    ss[tid] = s; sqs[tid] = q;
    __syncthreads();
    for (int o = 128; o > 0; o >>= 1) {
        if (tid < o) { ss[tid] += ss[tid + o]; sqs[tid] += sqs[tid + o]; }
        __syncthreads();
    }
    if (tid == 0) {
        const float n = (float)(BB * TT);
        const float mean = ss[0] / n;
        const float var = sqs[0] / n - mean * mean;
        g_stats[ch * 2]     = mean;
        g_stats[ch * 2 + 1] = rsqrtf(fmaxf(var, 0.0f) + 1e-5f);
    }
}

__global__ void gate_add(const float* __restrict__ H1,
                         const float* __restrict__ x4,
                         float* __restrict__ Hp)
{
    const int idx = blockIdx.x * 256 + threadIdx.x;
    if (idx >= BB * TT * HH) return;
    const int row = idx / HH;
    const int b = row / TT, t = row % TT;
    const float xv = (x4[(size_t)b * TT + t] - g_stats[0]) * g_stats[1];
    Hp[idx] = H1[idx] + fsig(xv);
}

__global__ void final_fc(const float* __restrict__ out2,
                         const float* __restrict__ fc1w, const float* __restrict__ fc1b,
                         const float* __restrict__ fc2w, const float* __restrict__ fc2b,
                         float* __restrict__ dout)
{
    __shared__ float we[HH];
    __shared__ float beff;
    const int tid = threadIdx.x;
    if (tid < HH) {
        float s = 0.0f;
        for (int k = 0; k < HH; k++) s = fmaf(fc2w[k], fc1w[k * HH + tid], s);
        we[tid] = s;
    }
    if (tid == 64) {
        float s = fc2b[0];
        for (int k = 0; k < HH; k++) s = fmaf(fc1b[k], fc2w[k], s);
        beff = s;
    }
    __syncthreads();
    const int warp = tid >> 5, lane = tid & 31;
    const int base = blockIdx.x * 128 + warp * 16;
#pragma unroll 1
    for (int r = 0; r < 16; r++) {
        const int row = base + r;
        const float* xr = out2 + (size_t)row * HH;
        float v = xr[lane] * we[lane] + xr[lane + 32] * we[lane + 32];
#pragma unroll
        for (int o = 16; o > 0; o >>= 1) v += __shfl_xor_sync(0xffffffffu, v, o);
        if (lane == 0) dout[row] = fsig(v + beff);
    }
}

// ---------------------------------------------------------------------------
extern "C" void kernel_launch(void* const* d_in, const int* in_sizes, int n_in,
                              void* d_out, int out_size)
{
    const float* data  = (const float*)d_in[0];
    const float* h01   = (const float*)d_in[1];
    const float* c01   = (const float*)d_in[2];
    const float* h02   = (const float*)d_in[3];
    const float* c02   = (const float*)d_in[4];
    const float* Wih0  = (const float*)d_in[5];   // [256,40]
    const float* Wih12 = (const float*)d_in[6];   // [2,256,64]
    const float* l1Whh = (const float*)d_in[7];   // [3,256,64]
    const float* l1b   = (const float*)d_in[8];   // [3,256]
    const float* l2Wih = (const float*)d_in[9];   // [3,256,64]
    const float* l2Whh = (const float*)d_in[10];  // [3,256,64]
    const float* l2b   = (const float*)d_in[11];  // [3,256]
    const float* cw1 = (const float*)d_in[12];
    const float* cb1 = (const float*)d_in[13];
    const float* cw2 = (const float*)d_in[14];
    const float* cb2 = (const float*)d_in[15];
    const float* cw3 = (const float*)d_in[16];
    const float* cb3 = (const float*)d_in[17];
    const float* cw4 = (const float*)d_in[18];
    const float* cb4 = (const float*)d_in[19];
    const float* fc1w = (const float*)d_in[20];
    const float* fc1b = (const float*)d_in[21];
    const float* fc2w = (const float*)d_in[22];
    const float* fc2b = (const float*)d_in[23];
    float* out = (float*)d_out;

    float *bufA, *bufB, *att, *cva, *cvb, *stats;
    cudaGetSymbolAddress((void**)&bufA, g_bufA);
    cudaGetSymbolAddress((void**)&bufB, g_bufB);
    cudaGetSymbolAddress((void**)&att,  g_att);
    cudaGetSymbolAddress((void**)&cva,  g_cva);
    cudaGetSymbolAddress((void**)&cvb,  g_cvb);
    cudaGetSymbolAddress((void**)&stats, g_stats);

    const int GEMM_GRID = BB * TT / 16;

    // ----- stack 1 (phase-launched wavefront over 3 layers) -----
    xg_gemm<DD1, 16><<<GEMM_GRID, 256>>>(data, Wih0, l1b);
    init_state<<<1, 384>>>(h01, c01);
    for (int ph = 0; ph < NPH; ph++)
        stack_phase<<<6, 256>>>(ph, l1Whh, Wih12, l1b + GG, bufA);

    // ----- attention conv gate -----
    att_stats<<<BB * TT / 8, 256>>>(bufA, att);
    conv1d_k<<<(BB * 3 * TT + 255) / 256, 256>>>(att, 3, cw1, cb1, 3, nullptr, 0, cva);
    bn_stats<<<3, 256>>>(cva, 3);
    conv1d_k<<<(BB * 5 * TT + 255) / 256, 256>>>(cva, 3, cw2, cb2, 5, stats, 1, cvb);
    bn_stats<<<5, 256>>>(cvb, 5);
    conv1d_k<<<(BB * 5 * TT + 255) / 256, 256>>>(cvb, 5, cw3, cb3, 5, stats, 1, cva);
    bn_stats<<<5, 256>>>(cva, 5);
    conv1d_k<<<(BB * 1 * TT + 255) / 256, 256>>>(cva, 5, cw4, cb4, 1, stats, 1, cvb);
    bn_stats<<<1, 256>>>(cvb, 1);
    gate_add<<<BB * TT * HH / 256, 256>>>(bufA, cvb, bufB);

    // ----- stack 2 (phase-launched wavefront over 3 layers) -----
    xg_gemm<HH, 16><<<GEMM_GRID, 256>>>(bufB, l2Wih, l2b);
    init_state<<<1, 384>>>(h02, c02);
    for (int ph = 0; ph < NPH; ph++)
        stack_phase<<<6, 256>>>(ph, l2Whh, l2Wih + GG * HH, l2b + GG, bufA);

    // ----- head -----
    final_fc<<<BB * TT / 128, 256>>>(bufA, fc1w, fc1b, fc2w, fc2b, out);
}